// round 2
// baseline (speedup 1.0000x reference)
#include <cuda_runtime.h>
#include <cuda_bf16.h>

// Problem constants
#define BATCH   2
#define SEQ     2048
#define DMODEL  1024
#define NHEAD   16
#define DK      64
#define BH      (BATCH * NHEAD)              // 32
#define TOKENS  (BATCH * SEQ)                // 4096
#define OUT0    (TOKENS * DMODEL)            // 4,194,304
#define ATTN_N  (BH * SEQ * SEQ)             // 134,217,728
#define OUT_TOTAL (OUT0 + ATTN_N)            // 138,412,032

// Scratch (static device arrays; no cudaMalloc anywhere)
__device__ float g_q[BH * SEQ * DK];     // [B,H,S,dk]
__device__ float g_k[BH * SEQ * DK];
__device__ float g_v[BH * SEQ * DK];
__device__ float g_ctx[TOKENS * DMODEL]; // [B,S,D] (heads re-interleaved)
__device__ float g_attn[ATTN_N];         // fallback if d_out doesn't hold attn

// ---------------------------------------------------------------------------
// Generic tiled SGEMM:  C = A * (TRANS_B ? B^T : B)  with epilogue MODE.
// A: [M,K] row-major (lda).  B: TRANS_B ? [N,K] : [K,N] row-major (ldb).
// MODE 0: plain store (+bias[col] if bias != nullptr)
// MODE 1: head-split scatter for projections: row r -> (b,s), col c -> (h,j),
//         store into [B,H,S,dk]; bias added.
// MODE 2: scale by `scale`, plain store (scores).
// MODE 3: context store: per batch z=(b*16+h), C base += b*S*D + h*64, ldc=D.
// Tiles: 64x64x16, 256 threads, 4x4 microtile per thread.
// ---------------------------------------------------------------------------
#define TBM 64
#define TBN 64
#define TBK 16

template <bool TRANS_B, int MODE>
__global__ void __launch_bounds__(256)
gemm_k(const float* __restrict__ A, const float* __restrict__ Bm,
       const float* __restrict__ bias, float* __restrict__ C,
       int M, int N, int K, int lda, int ldb, int ldc,
       long sA, long sB, long sC, float scale)
{
    const int z = blockIdx.z;
    A  += (long)z * sA;
    Bm += (long)z * sB;
    if (MODE == 3) {
        C += (long)(z >> 4) * ((long)SEQ * DMODEL) + (long)(z & 15) * DK;
    } else {
        C += (long)z * sC;
    }

    const int m0 = blockIdx.y * TBM;
    const int n0 = blockIdx.x * TBN;

    __shared__ float As[TBK][TBM];
    __shared__ float Bs[TBK][TBN];

    const int tid = threadIdx.x;
    const int tx = tid & 15;   // col group
    const int ty = tid >> 4;   // row group

    float acc[4][4];
#pragma unroll
    for (int i = 0; i < 4; i++)
#pragma unroll
        for (int j = 0; j < 4; j++) acc[i][j] = 0.0f;

    for (int kt = 0; kt < K; kt += TBK) {
        // Load A tile (64 rows x 16 k) : As[k][m]
#pragma unroll
        for (int e = 0; e < 4; e++) {
            int i = tid + e * 256;          // 0..1023
            int am = i >> 4, ak = i & 15;
            As[ak][am] = A[(long)(m0 + am) * lda + kt + ak];
            if (TRANS_B) {
                Bs[ak][am] = Bm[(long)(n0 + am) * ldb + kt + ak];
            } else {
                int bk = i >> 6, bn = i & 63;
                Bs[bk][bn] = Bm[(long)(kt + bk) * ldb + n0 + bn];
            }
        }
        __syncthreads();

#pragma unroll
        for (int k = 0; k < TBK; k++) {
            float4 av = *(const float4*)&As[k][ty * 4];
            float4 bv = *(const float4*)&Bs[k][tx * 4];
            float a[4] = {av.x, av.y, av.z, av.w};
            float b[4] = {bv.x, bv.y, bv.z, bv.w};
#pragma unroll
            for (int i = 0; i < 4; i++)
#pragma unroll
                for (int j = 0; j < 4; j++)
                    acc[i][j] = fmaf(a[i], b[j], acc[i][j]);
        }
        __syncthreads();
    }

    // Epilogue
#pragma unroll
    for (int i = 0; i < 4; i++) {
#pragma unroll
        for (int j = 0; j < 4; j++) {
            int r = m0 + ty * 4 + i;
            int c = n0 + tx * 4 + j;
            float v = acc[i][j];
            if (MODE == 0) {
                if (bias) v += bias[c];
                C[(long)r * ldc + c] = v;
            } else if (MODE == 1) {
                v += bias[c];
                int h = c >> 6, jj = c & 63;
                int b = r >> 11, s = r & 2047;           // S = 2048
                C[((((long)b * NHEAD + h) * SEQ) + s) * DK + jj] = v;
            } else if (MODE == 2) {
                C[(long)r * ldc + c] = v * scale;
            } else { // MODE 3
                C[(long)r * ldc + c] = v;
            }
        }
    }
}

// ---------------------------------------------------------------------------
// Row softmax over attn [rows = BH*SEQ, width = SEQ=2048], in place.
// 256 threads/row, 8 elements/thread via float4.
// ---------------------------------------------------------------------------
__global__ void __launch_bounds__(256)
softmax_k(float* __restrict__ attn)
{
    const long row = blockIdx.x;
    float4* p = (float4*)(attn + row * (long)SEQ);   // 512 float4
    const int tid = threadIdx.x;
    const int lane = tid & 31, warp = tid >> 5;

    float4 v0 = p[tid];
    float4 v1 = p[tid + 256];

    float mx = fmaxf(fmaxf(fmaxf(v0.x, v0.y), fmaxf(v0.z, v0.w)),
                     fmaxf(fmaxf(v1.x, v1.y), fmaxf(v1.z, v1.w)));
#pragma unroll
    for (int off = 16; off > 0; off >>= 1)
        mx = fmaxf(mx, __shfl_xor_sync(0xffffffffu, mx, off));

    __shared__ float red_max[8];
    __shared__ float red_sum[8];
    if (lane == 0) red_max[warp] = mx;
    __syncthreads();
    float bm = red_max[0];
#pragma unroll
    for (int w = 1; w < 8; w++) bm = fmaxf(bm, red_max[w]);

    v0.x = __expf(v0.x - bm); v0.y = __expf(v0.y - bm);
    v0.z = __expf(v0.z - bm); v0.w = __expf(v0.w - bm);
    v1.x = __expf(v1.x - bm); v1.y = __expf(v1.y - bm);
    v1.z = __expf(v1.z - bm); v1.w = __expf(v1.w - bm);

    float sum = v0.x + v0.y + v0.z + v0.w + v1.x + v1.y + v1.z + v1.w;
#pragma unroll
    for (int off = 16; off > 0; off >>= 1)
        sum += __shfl_xor_sync(0xffffffffu, sum, off);
    if (lane == 0) red_sum[warp] = sum;
    __syncthreads();
    float bs = 0.0f;
#pragma unroll
    for (int w = 0; w < 8; w++) bs += red_sum[w];
    float inv = 1.0f / bs;

    v0.x *= inv; v0.y *= inv; v0.z *= inv; v0.w *= inv;
    v1.x *= inv; v1.y *= inv; v1.z *= inv; v1.w *= inv;
    p[tid] = v0;
    p[tid + 256] = v1;
}

// ---------------------------------------------------------------------------
extern "C" void kernel_launch(void* const* d_in, const int* in_sizes, int n_in,
                              void* d_out, int out_size)
{
    const float* Q  = (const float*)d_in[0];
    const float* K  = (const float*)d_in[1];
    const float* V  = (const float*)d_in[2];
    const float* Wq = (const float*)d_in[3];
    const float* bq = (const float*)d_in[4];
    const float* Wk = (const float*)d_in[5];
    const float* bk = (const float*)d_in[6];
    const float* Wv = (const float*)d_in[7];
    const float* bv = (const float*)d_in[8];
    const float* Wo = (const float*)d_in[9];
    const float* bo = (const float*)d_in[10];

    float* out = (float*)d_out;

    float* q;   cudaGetSymbolAddress((void**)&q,   g_q);
    float* k;   cudaGetSymbolAddress((void**)&k,   g_k);
    float* v;   cudaGetSymbolAddress((void**)&v,   g_v);
    float* ctx; cudaGetSymbolAddress((void**)&ctx, g_ctx);
    float* attn_scratch; cudaGetSymbolAddress((void**)&attn_scratch, g_attn);

    float* attn = (out_size >= OUT_TOTAL) ? (out + OUT0) : attn_scratch;

    const float inv_scale = 0.125f;  // 1/sqrt(64)

    // 1-3) Projections: [4096,1024] @ W^T + b, scattered to [B,H,S,dk]
    dim3 gproj(DMODEL / TBN, TOKENS / TBM, 1);   // (16, 64, 1)
    gemm_k<true, 1><<<gproj, 256>>>(Q, Wq, bq, q, TOKENS, DMODEL, DMODEL,
                                    DMODEL, DMODEL, 0, 0, 0, 0, 0.0f);
    gemm_k<true, 1><<<gproj, 256>>>(K, Wk, bk, k, TOKENS, DMODEL, DMODEL,
                                    DMODEL, DMODEL, 0, 0, 0, 0, 0.0f);
    gemm_k<true, 1><<<gproj, 256>>>(V, Wv, bv, v, TOKENS, DMODEL, DMODEL,
                                    DMODEL, DMODEL, 0, 0, 0, 0, 0.0f);

    // 4) Scores: per (b,h): [2048,64] @ [2048,64]^T * (1/8) -> attn [2048,2048]
    dim3 gsc(SEQ / TBN, SEQ / TBM, BH);          // (32, 32, 32)
    gemm_k<true, 2><<<gsc, 256>>>(q, k, nullptr, attn, SEQ, SEQ, DK,
                                  DK, DK, SEQ,
                                  (long)SEQ * DK, (long)SEQ * DK,
                                  (long)SEQ * SEQ, inv_scale);

    // 5) Softmax rows (in place, also produces the required attn output)
    softmax_k<<<BH * SEQ, 256>>>(attn);

    // 6) Context: per (b,h): attn[2048,2048] @ v[2048,64] -> ctx [B,S,D]
    dim3 gctx(DK / TBN, SEQ / TBM, BH);          // (1, 32, 32)
    gemm_k<false, 3><<<gctx, 256>>>(attn, v, nullptr, ctx, SEQ, DK, SEQ,
                                    SEQ, DK, DMODEL,
                                    (long)SEQ * SEQ, (long)SEQ * DK, 0, 0.0f);

    // 7) Output projection: ctx [4096,1024] @ Wo^T + bo -> out[0:OUT0)
    dim3 gout(DMODEL / TBN, TOKENS / TBM, 1);
    gemm_k<true, 0><<<gout, 256>>>(ctx, Wo, bo, out, TOKENS, DMODEL, DMODEL,
                                   DMODEL, DMODEL, DMODEL, 0, 0, 0, 0.0f);

    (void)n_in; (void)in_sizes;
}

// round 4
// speedup vs baseline: 2.3825x; 2.3825x over previous
#include <cuda_runtime.h>
#include <cuda_bf16.h>
#include <cstdint>

// ---------------------------------------------------------------------------
// Problem constants
// ---------------------------------------------------------------------------
#define BATCH   2
#define SEQ     2048
#define DMODEL  1024
#define NHEAD   16
#define DK      64
#define BH      (BATCH * NHEAD)              // 32
#define TOKENS  (BATCH * SEQ)                // 4096
#define OUT0    (TOKENS * DMODEL)            // 4,194,304
#define ATTN_N  ((long)BH * SEQ * SEQ)       // 134,217,728
#define OUT_TOTAL (OUT0 + ATTN_N)

// ---------------------------------------------------------------------------
// Scratch (static device arrays; no cudaMalloc anywhere)
// ---------------------------------------------------------------------------
__device__ __nv_bfloat16 g_Qh[TOKENS * DMODEL], g_Ql[TOKENS * DMODEL];
__device__ __nv_bfloat16 g_Kh[TOKENS * DMODEL], g_Kl[TOKENS * DMODEL];
__device__ __nv_bfloat16 g_Vh[TOKENS * DMODEL], g_Vl[TOKENS * DMODEL];
__device__ __nv_bfloat16 g_Wqh[DMODEL * DMODEL], g_Wql[DMODEL * DMODEL];
__device__ __nv_bfloat16 g_Wkh[DMODEL * DMODEL], g_Wkl[DMODEL * DMODEL];
__device__ __nv_bfloat16 g_Wvh[DMODEL * DMODEL], g_Wvl[DMODEL * DMODEL];
__device__ __nv_bfloat16 g_Woh[DMODEL * DMODEL], g_Wol[DMODEL * DMODEL];
__device__ __nv_bfloat16 g_qh[TOKENS * DMODEL], g_ql[TOKENS * DMODEL];   // [B,S,H*64]
__device__ __nv_bfloat16 g_kh[TOKENS * DMODEL], g_kl[TOKENS * DMODEL];   // [B,S,H*64]
__device__ __nv_bfloat16 g_vth[BH * DK * SEQ], g_vtl[BH * DK * SEQ];     // [BH,64,S]
__device__ __nv_bfloat16 g_ch[TOKENS * DMODEL], g_cl[TOKENS * DMODEL];   // ctx [B,S,D]
__device__ float g_attn[ATTN_N];                 // fallback if d_out lacks attn

// ---------------------------------------------------------------------------
// Helpers
// ---------------------------------------------------------------------------
__device__ __forceinline__ uint32_t smem_u32(const void* p) {
    uint32_t a;
    asm("{ .reg .u64 t; cvta.to.shared.u64 t, %1; cvt.u32.u64 %0, t; }"
        : "=r"(a) : "l"(p));
    return a;
}
#define SWZ(off) ((off) ^ (((off) >> 3) & 0x70))

__device__ __forceinline__ void ldsm_x4(uint32_t& r0, uint32_t& r1,
                                        uint32_t& r2, uint32_t& r3, uint32_t a) {
    asm volatile("ldmatrix.sync.aligned.m8n8.x4.shared.b16 {%0,%1,%2,%3}, [%4];"
                 : "=r"(r0), "=r"(r1), "=r"(r2), "=r"(r3) : "r"(a));
}
__device__ __forceinline__ void mma16816(float* c, const uint32_t* a,
                                         uint32_t b0, uint32_t b1) {
    asm volatile(
        "mma.sync.aligned.m16n8k16.row.col.f32.bf16.bf16.f32 "
        "{%0,%1,%2,%3}, {%4,%5,%6,%7}, {%8,%9}, {%0,%1,%2,%3};"
        : "+f"(c[0]), "+f"(c[1]), "+f"(c[2]), "+f"(c[3])
        : "r"(a[0]), "r"(a[1]), "r"(a[2]), "r"(a[3]), "r"(b0), "r"(b1));
}

// ---------------------------------------------------------------------------
// fp32 -> bf16 hi/lo split (pre-pass for all GEMM inputs)
// ---------------------------------------------------------------------------
__global__ void __launch_bounds__(256)
split_k(const float* __restrict__ x, __nv_bfloat16* __restrict__ h,
        __nv_bfloat16* __restrict__ l, int n)
{
    int i = blockIdx.x * 256 + threadIdx.x;
    if (i < n) {
        float v = x[i];
        __nv_bfloat16 hv = __float2bfloat16(v);
        h[i] = hv;
        l[i] = __float2bfloat16(v - __bfloat162float(hv));
    }
}

// ---------------------------------------------------------------------------
// mma.sync split-bf16 GEMM.  Tile M=128, N=64, K-tile=64; 256 threads (8 warps,
// 4x2 warp grid, 32x32 per warp).  C = A @ B^T, both K-major SW128 in smem.
// 3 HMMA passes per fragment (hi*hi + lo*hi + hi*lo), fp32 accum in registers.
// ASRC: 0 = pre-split bf16 arrays (A0=hi, A1=lo); 1 = fp32 (A0), split in-kernel.
// EPI:  0 LIN (bias + split store, ld 1024)            [Q/K projections]
//       1 VT  (bias + split store transposed per-head) [V projection]
//       2 SCORES (scale, fp32 store ld 2048, z-offset) [q@k^T]
//       3 CTX (split store head-interleaved [B,S,D])   [attn@v]
//       4 OUT (bias, fp32 store ld 1024)               [output projection]
// ---------------------------------------------------------------------------
#define MT 128
#define NT 64
#define KT 64
#define SM_AH   0
#define SM_AL   16384
#define SM_BH   32768
#define SM_BL   40960
#define SM_TOTAL 49152

template <int ASRC, int EPI>
__global__ void __launch_bounds__(256)
mma_gemm(const void* A0, const void* A1,
         const __nv_bfloat16* __restrict__ B0, const __nv_bfloat16* __restrict__ B1,
         const float* __restrict__ bias, float* __restrict__ outF,
         __nv_bfloat16* __restrict__ outH, __nv_bfloat16* __restrict__ outL,
         int K, int lda, int ldb, float scale)
{
    extern __shared__ uint8_t dsm[];
    const uint32_t sb = smem_u32(dsm);
    const int tid = threadIdx.x, wid = tid >> 5, lane = tid & 31;
    const int wm = wid >> 1, wn = wid & 1;           // 4 x 2 warp grid
    const int z = blockIdx.z;
    const int n0 = blockIdx.x * NT, m0 = blockIdx.y * MT;

    long offA = 0, offB = 0;
    if (EPI == 2) { offA = offB = (long)(z >> 4) * (2048L * 1024) + (long)(z & 15) * 64; }
    if (EPI == 3) { offA = (long)z * 2048L * 2048; offB = (long)z * 64L * 2048; }

    const __nv_bfloat16* Ah = (ASRC == 0) ? ((const __nv_bfloat16*)A0) + offA : nullptr;
    const __nv_bfloat16* Al = (ASRC == 0) ? ((const __nv_bfloat16*)A1) + offA : nullptr;
    const float*         Af = (ASRC == 1) ? ((const float*)A0) + offA : nullptr;
    const __nv_bfloat16* Bh = B0 + offB;
    const __nv_bfloat16* Bl = B1 + offB;

    float acc[2][4][4];
#pragma unroll
    for (int i = 0; i < 2; i++)
#pragma unroll
        for (int j = 0; j < 4; j++)
#pragma unroll
            for (int r = 0; r < 4; r++) acc[i][j][r] = 0.0f;

    // per-lane ldmatrix base offsets
    const int lrow = lane & 15, lkh = lane >> 4;     // row-in-16, k-half

    for (int kt = 0; kt < K; kt += KT) {
        if (kt) __syncthreads();
        // ---- stage A tile (128 x 64) hi/lo ----
        if (ASRC == 0) {
#pragma unroll 4
            for (int i = tid; i < MT * KT / 2; i += 256) {
                int row = i >> 5, cp = i & 31;
                long g = (long)(m0 + row) * lda + kt + cp * 2;
                uint32_t hv = *(const uint32_t*)(Ah + g);
                uint32_t lv = *(const uint32_t*)(Al + g);
                uint32_t so = SWZ(row * 128 + cp * 4);
                *(uint32_t*)(dsm + SM_AH + so) = hv;
                *(uint32_t*)(dsm + SM_AL + so) = lv;
            }
        } else {
#pragma unroll 4
            for (int i = tid; i < MT * KT / 2; i += 256) {
                int row = i >> 5, cp = i & 31;
                float2 f = *(const float2*)(Af + (long)(m0 + row) * lda + kt + cp * 2);
                __nv_bfloat16 h0 = __float2bfloat16(f.x), h1 = __float2bfloat16(f.y);
                __nv_bfloat16 l0 = __float2bfloat16(f.x - __bfloat162float(h0));
                __nv_bfloat16 l1 = __float2bfloat16(f.y - __bfloat162float(h1));
                uint32_t hv = (uint32_t)__bfloat16_as_ushort(h0) |
                              ((uint32_t)__bfloat16_as_ushort(h1) << 16);
                uint32_t lv = (uint32_t)__bfloat16_as_ushort(l0) |
                              ((uint32_t)__bfloat16_as_ushort(l1) << 16);
                uint32_t so = SWZ(row * 128 + cp * 4);
                *(uint32_t*)(dsm + SM_AH + so) = hv;
                *(uint32_t*)(dsm + SM_AL + so) = lv;
            }
        }
        // ---- stage B tile (64 x 64) hi/lo ----
#pragma unroll 4
        for (int i = tid; i < NT * KT / 2; i += 256) {
            int row = i >> 5, cp = i & 31;
            long g = (long)(n0 + row) * ldb + kt + cp * 2;
            uint32_t hv = *(const uint32_t*)(Bh + g);
            uint32_t lv = *(const uint32_t*)(Bl + g);
            uint32_t so = SWZ(row * 128 + cp * 4);
            *(uint32_t*)(dsm + SM_BH + so) = hv;
            *(uint32_t*)(dsm + SM_BL + so) = lv;
        }
        __syncthreads();

        // ---- compute: 4 k16 steps ----
#pragma unroll
        for (int ks = 0; ks < 4; ks++) {
            const uint32_t kb = ks * 32 + lkh * 16;
            uint32_t ah[2][4], al[2][4];
#pragma unroll
            for (int ms = 0; ms < 2; ms++) {
                uint32_t ro = (uint32_t)(wm * 32 + ms * 16 + lrow) * 128 + kb;
                ldsm_x4(ah[ms][0], ah[ms][1], ah[ms][2], ah[ms][3], sb + SM_AH + SWZ(ro));
                ldsm_x4(al[ms][0], al[ms][1], al[ms][2], al[ms][3], sb + SM_AL + SWZ(ro));
            }
            uint32_t bh[4][2], bl[4][2];
#pragma unroll
            for (int half = 0; half < 2; half++) {
                uint32_t ro = (uint32_t)(wn * 32 + half * 16 + lrow) * 128 + kb;
                uint32_t r0, r1, r2, r3;
                ldsm_x4(r0, r1, r2, r3, sb + SM_BH + SWZ(ro));
                bh[half * 2 + 0][0] = r0; bh[half * 2 + 0][1] = r2;
                bh[half * 2 + 1][0] = r1; bh[half * 2 + 1][1] = r3;
                ldsm_x4(r0, r1, r2, r3, sb + SM_BL + SWZ(ro));
                bl[half * 2 + 0][0] = r0; bl[half * 2 + 0][1] = r2;
                bl[half * 2 + 1][0] = r1; bl[half * 2 + 1][1] = r3;
            }
#pragma unroll
            for (int ms = 0; ms < 2; ms++)
#pragma unroll
                for (int nb = 0; nb < 4; nb++) {
                    mma16816(acc[ms][nb], ah[ms], bh[nb][0], bh[nb][1]);
                    mma16816(acc[ms][nb], al[ms], bh[nb][0], bh[nb][1]);
                    mma16816(acc[ms][nb], ah[ms], bl[nb][0], bl[nb][1]);
                }
        }
    }
    __syncthreads();

    // ---- epilogue: regs -> padded smem staging -> coalesced global ----
    float* st = (float*)dsm;                     // [128][65] fp32 (33280 B)
    {
        const int lr = lane >> 2, lc = (lane & 3) * 2;
#pragma unroll
        for (int ms = 0; ms < 2; ms++)
#pragma unroll
            for (int nb = 0; nb < 4; nb++) {
                int r = wm * 32 + ms * 16 + lr;
                int c = wn * 32 + nb * 8 + lc;
                st[r * 65 + c]            = acc[ms][nb][0];
                st[r * 65 + c + 1]        = acc[ms][nb][1];
                st[(r + 8) * 65 + c]      = acc[ms][nb][2];
                st[(r + 8) * 65 + c + 1]  = acc[ms][nb][3];
            }
    }
    __syncthreads();

    if (EPI == 2) {            // SCORES: fp32, ld 2048, z block
        for (int i = tid; i < MT * NT; i += 256) {
            int row = i >> 6, c = i & 63;
            outF[(long)z * 2048L * 2048 + (long)(m0 + row) * 2048 + n0 + c] =
                st[row * 65 + c] * scale;
        }
    } else if (EPI == 4) {     // OUT: fp32 + bias, ld 1024
        for (int i = tid; i < MT * NT; i += 256) {
            int row = i >> 6, c = i & 63;
            outF[(long)(m0 + row) * 1024 + n0 + c] = st[row * 65 + c] + bias[n0 + c];
        }
    } else if (EPI == 0) {     // LIN: bias + split, ld 1024
        for (int i = tid; i < MT * NT; i += 256) {
            int row = i >> 6, c = i & 63;
            float v = st[row * 65 + c] + bias[n0 + c];
            long o = (long)(m0 + row) * 1024 + n0 + c;
            __nv_bfloat16 h = __float2bfloat16(v);
            outH[o] = h;
            outL[o] = __float2bfloat16(v - __bfloat162float(h));
        }
    } else if (EPI == 1) {     // VT: bias + split, transposed per-head [BH,64,S]
        for (int i = tid; i < MT * NT; i += 256) {
            int j = i >> 7, rl = i & 127;
            int r = m0 + rl, cg = n0 + j;
            float v = st[rl * 65 + j] + bias[cg];
            int b = r >> 11, s = r & 2047, hh = cg >> 6, jj = cg & 63;
            long o = ((long)(b * 16 + hh) * 64 + jj) * 2048 + s;
            __nv_bfloat16 h = __float2bfloat16(v);
            outH[o] = h;
            outL[o] = __float2bfloat16(v - __bfloat162float(h));
        }
    } else {                   // CTX: split, [B,S,D] head-interleave (n0 == 0)
        int b = z >> 4, hh = z & 15;
        for (int i = tid; i < MT * NT; i += 256) {
            int row = i >> 6, c = i & 63;
            float v = st[row * 65 + c];
            long o = (long)((b << 11) + m0 + row) * 1024 + hh * 64 + c;
            __nv_bfloat16 h = __float2bfloat16(v);
            outH[o] = h;
            outL[o] = __float2bfloat16(v - __bfloat162float(h));
        }
    }
    (void)scale;
}

// ---------------------------------------------------------------------------
// Row softmax over attn [BH*SEQ rows, SEQ cols], in place
// ---------------------------------------------------------------------------
__global__ void __launch_bounds__(256)
softmax_k(float* __restrict__ attn)
{
    const long row = blockIdx.x;
    float4* p = (float4*)(attn + row * (long)SEQ);
    const int tid = threadIdx.x;
    const int lane = tid & 31, warp = tid >> 5;

    float4 v0 = p[tid];
    float4 v1 = p[tid + 256];

    float mx = fmaxf(fmaxf(fmaxf(v0.x, v0.y), fmaxf(v0.z, v0.w)),
                     fmaxf(fmaxf(v1.x, v1.y), fmaxf(v1.z, v1.w)));
#pragma unroll
    for (int off = 16; off > 0; off >>= 1)
        mx = fmaxf(mx, __shfl_xor_sync(0xffffffffu, mx, off));

    __shared__ float red_max[8];
    __shared__ float red_sum[8];
    if (lane == 0) red_max[warp] = mx;
    __syncthreads();
    float bm = red_max[0];
#pragma unroll
    for (int w = 1; w < 8; w++) bm = fmaxf(bm, red_max[w]);

    v0.x = __expf(v0.x - bm); v0.y = __expf(v0.y - bm);
    v0.z = __expf(v0.z - bm); v0.w = __expf(v0.w - bm);
    v1.x = __expf(v1.x - bm); v1.y = __expf(v1.y - bm);
    v1.z = __expf(v1.z - bm); v1.w = __expf(v1.w - bm);

    float sum = v0.x + v0.y + v0.z + v0.w + v1.x + v1.y + v1.z + v1.w;
#pragma unroll
    for (int off = 16; off > 0; off >>= 1)
        sum += __shfl_xor_sync(0xffffffffu, sum, off);
    if (lane == 0) red_sum[warp] = sum;
    __syncthreads();
    float bs = 0.0f;
#pragma unroll
    for (int w = 0; w < 8; w++) bs += red_sum[w];
    float inv = 1.0f / bs;

    v0.x *= inv; v0.y *= inv; v0.z *= inv; v0.w *= inv;
    v1.x *= inv; v1.y *= inv; v1.z *= inv; v1.w *= inv;
    p[tid] = v0;
    p[tid + 256] = v1;
}

// ---------------------------------------------------------------------------
extern "C" void kernel_launch(void* const* d_in, const int* in_sizes, int n_in,
                              void* d_out, int out_size)
{
    const float* Q  = (const float*)d_in[0];
    const float* K  = (const float*)d_in[1];
    const float* V  = (const float*)d_in[2];
    const float* Wq = (const float*)d_in[3];
    const float* bq = (const float*)d_in[4];
    const float* Wk = (const float*)d_in[5];
    const float* bk = (const float*)d_in[6];
    const float* Wv = (const float*)d_in[7];
    const float* bv = (const float*)d_in[8];
    const float* Wo = (const float*)d_in[9];
    const float* bo = (const float*)d_in[10];
    float* out = (float*)d_out;

    __nv_bfloat16 *Qh, *Ql, *Kh, *Kl, *Vh, *Vl;
    __nv_bfloat16 *Wqh, *Wql, *Wkh, *Wkl, *Wvh, *Wvl, *Woh, *Wol;
    __nv_bfloat16 *qh, *ql, *kh, *kl, *vth, *vtl, *ch, *cl;
    float* attn_scratch;
    cudaGetSymbolAddress((void**)&Qh, g_Qh);   cudaGetSymbolAddress((void**)&Ql, g_Ql);
    cudaGetSymbolAddress((void**)&Kh, g_Kh);   cudaGetSymbolAddress((void**)&Kl, g_Kl);
    cudaGetSymbolAddress((void**)&Vh, g_Vh);   cudaGetSymbolAddress((void**)&Vl, g_Vl);
    cudaGetSymbolAddress((void**)&Wqh, g_Wqh); cudaGetSymbolAddress((void**)&Wql, g_Wql);
    cudaGetSymbolAddress((void**)&Wkh, g_Wkh); cudaGetSymbolAddress((void**)&Wkl, g_Wkl);
    cudaGetSymbolAddress((void**)&Wvh, g_Wvh); cudaGetSymbolAddress((void**)&Wvl, g_Wvl);
    cudaGetSymbolAddress((void**)&Woh, g_Woh); cudaGetSymbolAddress((void**)&Wol, g_Wol);
    cudaGetSymbolAddress((void**)&qh, g_qh);   cudaGetSymbolAddress((void**)&ql, g_ql);
    cudaGetSymbolAddress((void**)&kh, g_kh);   cudaGetSymbolAddress((void**)&kl, g_kl);
    cudaGetSymbolAddress((void**)&vth, g_vth); cudaGetSymbolAddress((void**)&vtl, g_vtl);
    cudaGetSymbolAddress((void**)&ch, g_ch);   cudaGetSymbolAddress((void**)&cl, g_cl);
    cudaGetSymbolAddress((void**)&attn_scratch, g_attn);

    float* attn = ((long)out_size >= OUT_TOTAL) ? (out + OUT0) : attn_scratch;

    cudaFuncSetAttribute(mma_gemm<0, 0>, cudaFuncAttributeMaxDynamicSharedMemorySize, SM_TOTAL);
    cudaFuncSetAttribute(mma_gemm<0, 1>, cudaFuncAttributeMaxDynamicSharedMemorySize, SM_TOTAL);
    cudaFuncSetAttribute(mma_gemm<0, 2>, cudaFuncAttributeMaxDynamicSharedMemorySize, SM_TOTAL);
    cudaFuncSetAttribute(mma_gemm<1, 3>, cudaFuncAttributeMaxDynamicSharedMemorySize, SM_TOTAL);
    cudaFuncSetAttribute(mma_gemm<0, 4>, cudaFuncAttributeMaxDynamicSharedMemorySize, SM_TOTAL);

    // 0) Split all GEMM inputs to bf16 hi/lo
    const int NI = TOKENS * DMODEL, NW = DMODEL * DMODEL;
    split_k<<<NI / 256, 256>>>(Q, Qh, Ql, NI);
    split_k<<<NI / 256, 256>>>(K, Kh, Kl, NI);
    split_k<<<NI / 256, 256>>>(V, Vh, Vl, NI);
    split_k<<<NW / 256, 256>>>(Wq, Wqh, Wql, NW);
    split_k<<<NW / 256, 256>>>(Wk, Wkh, Wkl, NW);
    split_k<<<NW / 256, 256>>>(Wv, Wvh, Wvl, NW);
    split_k<<<NW / 256, 256>>>(Wo, Woh, Wol, NW);

    // 1-3) Projections: [4096,1024] @ W^T + b
    dim3 gp(DMODEL / NT, TOKENS / MT, 1);                       // (16, 32)
    mma_gemm<0, 0><<<gp, 256, SM_TOTAL>>>(Qh, Ql, Wqh, Wql, bq, nullptr, qh, ql,
                                          DMODEL, DMODEL, DMODEL, 0.f);
    mma_gemm<0, 0><<<gp, 256, SM_TOTAL>>>(Kh, Kl, Wkh, Wkl, bk, nullptr, kh, kl,
                                          DMODEL, DMODEL, DMODEL, 0.f);
    mma_gemm<0, 1><<<gp, 256, SM_TOTAL>>>(Vh, Vl, Wvh, Wvl, bv, nullptr, vth, vtl,
                                          DMODEL, DMODEL, DMODEL, 0.f);

    // 4) Scores: per head, q[2048,64] @ k[2048,64]^T / 8 -> attn fp32
    dim3 gs(SEQ / NT, SEQ / MT, BH);                            // (32, 16, 32)
    mma_gemm<0, 2><<<gs, 256, SM_TOTAL>>>(qh, ql, kh, kl, nullptr, attn, nullptr, nullptr,
                                          DK, DMODEL, DMODEL, 0.125f);

    // 5) Softmax (in place; produces the required attn output)
    softmax_k<<<BH * SEQ, 256>>>(attn);

    // 6) Context: per head, attn[2048,2048] @ vt[64,2048]^T -> ctx splits
    dim3 gc(1, SEQ / MT, BH);                                   // (1, 16, 32)
    mma_gemm<1, 3><<<gc, 256, SM_TOTAL>>>(attn, nullptr, vth, vtl, nullptr, nullptr,
                                          ch, cl, SEQ, SEQ, SEQ, 0.f);

    // 7) Output projection: ctx @ Wo^T + bo -> out fp32
    mma_gemm<0, 4><<<gp, 256, SM_TOTAL>>>(ch, cl, Woh, Wol, bo, out, nullptr, nullptr,
                                          DMODEL, DMODEL, DMODEL, 0.f);

    (void)n_in; (void)in_sizes;
}

// round 5
// speedup vs baseline: 3.2122x; 1.3482x over previous
#include <cuda_runtime.h>
#include <cuda_bf16.h>
#include <cstdint>

// ---------------------------------------------------------------------------
// Problem constants
// ---------------------------------------------------------------------------
#define BATCH   2
#define SEQ     2048
#define DMODEL  1024
#define NHEAD   16
#define DK      64
#define BH      (BATCH * NHEAD)              // 32
#define TOKENS  (BATCH * SEQ)                // 4096
#define OUT0    (TOKENS * DMODEL)            // 4,194,304
#define ATTN_N  ((long)BH * SEQ * SEQ)       // 134,217,728
#define OUT_TOTAL (OUT0 + ATTN_N)

// ---------------------------------------------------------------------------
// Scratch (static device arrays; no cudaMalloc anywhere)
// ---------------------------------------------------------------------------
__device__ __nv_bfloat16 g_Qh[TOKENS * DMODEL], g_Ql[TOKENS * DMODEL];
__device__ __nv_bfloat16 g_Kh[TOKENS * DMODEL], g_Kl[TOKENS * DMODEL];
__device__ __nv_bfloat16 g_Vh[TOKENS * DMODEL], g_Vl[TOKENS * DMODEL];
__device__ __nv_bfloat16 g_Wqh[DMODEL * DMODEL], g_Wql[DMODEL * DMODEL];
__device__ __nv_bfloat16 g_Wkh[DMODEL * DMODEL], g_Wkl[DMODEL * DMODEL];
__device__ __nv_bfloat16 g_Wvh[DMODEL * DMODEL], g_Wvl[DMODEL * DMODEL];
__device__ __nv_bfloat16 g_Woh[DMODEL * DMODEL], g_Wol[DMODEL * DMODEL];
__device__ __nv_bfloat16 g_qh[TOKENS * DMODEL], g_ql[TOKENS * DMODEL];   // [B,S,H*64]
__device__ __nv_bfloat16 g_kh[TOKENS * DMODEL], g_kl[TOKENS * DMODEL];   // [B,S,H*64]
__device__ __nv_bfloat16 g_vth[BH * DK * SEQ], g_vtl[BH * DK * SEQ];     // [BH,64,S]
__device__ __nv_bfloat16 g_ch[TOKENS * DMODEL], g_cl[TOKENS * DMODEL];   // ctx [B,S,D]
__device__ float g_attn[ATTN_N];                 // fallback if d_out lacks attn

// ---------------------------------------------------------------------------
// Helpers
// ---------------------------------------------------------------------------
__device__ __forceinline__ uint32_t smem_u32(const void* p) {
    uint32_t a;
    asm("{ .reg .u64 t; cvta.to.shared.u64 t, %1; cvt.u32.u64 %0, t; }"
        : "=r"(a) : "l"(p));
    return a;
}
#define SWZ(off) ((off) ^ (((off) >> 3) & 0x70))

__device__ __forceinline__ void ldsm_x4(uint32_t& r0, uint32_t& r1,
                                        uint32_t& r2, uint32_t& r3, uint32_t a) {
    asm volatile("ldmatrix.sync.aligned.m8n8.x4.shared.b16 {%0,%1,%2,%3}, [%4];"
                 : "=r"(r0), "=r"(r1), "=r"(r2), "=r"(r3) : "r"(a));
}
__device__ __forceinline__ void mma16816(float* c, const uint32_t* a,
                                         uint32_t b0, uint32_t b1) {
    asm volatile(
        "mma.sync.aligned.m16n8k16.row.col.f32.bf16.bf16.f32 "
        "{%0,%1,%2,%3}, {%4,%5,%6,%7}, {%8,%9}, {%0,%1,%2,%3};"
        : "+f"(c[0]), "+f"(c[1]), "+f"(c[2]), "+f"(c[3])
        : "r"(a[0]), "r"(a[1]), "r"(a[2]), "r"(a[3]), "r"(b0), "r"(b1));
}
__device__ __forceinline__ void cp16(uint32_t dst, const void* src) {
    asm volatile("cp.async.cg.shared.global [%0], [%1], 16;"
                 :: "r"(dst), "l"(src) : "memory");
}
#define CP_COMMIT() asm volatile("cp.async.commit_group;" ::: "memory")
#define CP_WAIT1()  asm volatile("cp.async.wait_group 1;" ::: "memory")
#define CP_WAIT0()  asm volatile("cp.async.wait_group 0;" ::: "memory")

// ---------------------------------------------------------------------------
// fp32 -> bf16 hi/lo split (pre-pass for GEMM inputs)
// ---------------------------------------------------------------------------
__global__ void __launch_bounds__(256)
split_k(const float* __restrict__ x, __nv_bfloat16* __restrict__ h,
        __nv_bfloat16* __restrict__ l, int n)
{
    int i = blockIdx.x * 256 + threadIdx.x;
    if (i < n) {
        float v = x[i];
        __nv_bfloat16 hv = __float2bfloat16(v);
        h[i] = hv;
        l[i] = __float2bfloat16(v - __bfloat162float(hv));
    }
}

// ---------------------------------------------------------------------------
// mma.sync split-bf16 GEMM.  Tile M=128, N=64, K-tile=64; 256 threads (8 warps,
// 4x2 warp grid, 32x32 per warp).  C = A @ B^T, K-major SW128 smem tiles.
// 3 HMMA passes per fragment (hi*hi + lo*hi + hi*lo), fp32 accum in registers.
// ASRC 0: pre-split bf16 operands, cp.async 2-stage pipelined mainloop.
// ASRC 1: fp32 A operand (attn), split in-kernel, synchronous loads.
// EPI:  0 LIN (bias + split store, ld 1024)            [Q/K projections]
//       1 VT  (bias + split store transposed per-head) [V projection]
//       3 CTX (split store head-interleaved [B,S,D])   [attn@v]
//       4 OUT (bias, fp32 store ld 1024)               [output projection]
// ---------------------------------------------------------------------------
#define MT 128
#define NT 64
#define KT 64
// pipelined (ASRC=0): two 48KB stages
#define STG_STRIDE 49152
#define OFF_AH 0
#define OFF_AL 16384
#define OFF_BH 32768
#define OFF_BL 40960
#define SM_PIPE  98304
#define SM_SYNC  49152

template <int ASRC, int EPI>
__global__ void __launch_bounds__(256)
mma_gemm(const void* A0, const void* A1,
         const __nv_bfloat16* __restrict__ B0, const __nv_bfloat16* __restrict__ B1,
         const float* __restrict__ bias, float* __restrict__ outF,
         __nv_bfloat16* __restrict__ outH, __nv_bfloat16* __restrict__ outL,
         int K, int lda, int ldb)
{
    extern __shared__ uint8_t dsm[];
    const uint32_t sb = smem_u32(dsm);
    const int tid = threadIdx.x, wid = tid >> 5, lane = tid & 31;
    const int wm = wid >> 1, wn = wid & 1;           // 4 x 2 warp grid
    const int z = blockIdx.z;
    const int n0 = blockIdx.x * NT, m0 = blockIdx.y * MT;

    long offA = 0, offB = 0;
    if (EPI == 3) { offA = (long)z * 2048L * 2048; offB = (long)z * 64L * 2048; }

    const __nv_bfloat16* Ah = (ASRC == 0) ? ((const __nv_bfloat16*)A0) + offA : nullptr;
    const __nv_bfloat16* Al = (ASRC == 0) ? ((const __nv_bfloat16*)A1) + offA : nullptr;
    const float*         Af = (ASRC == 1) ? ((const float*)A0) + offA : nullptr;
    const __nv_bfloat16* Bh = B0 + offB;
    const __nv_bfloat16* Bl = B1 + offB;

    float acc[2][4][4];
#pragma unroll
    for (int i = 0; i < 2; i++)
#pragma unroll
        for (int j = 0; j < 4; j++)
#pragma unroll
            for (int r = 0; r < 4; r++) acc[i][j][r] = 0.0f;

    const int lrow = lane & 15, lkh = lane >> 4;

    if (ASRC == 0) {
        // ---------------- pipelined mainloop (cp.async, 2 stages) ----------
        const int ntiles = K / KT;
        auto stage = [&](int kti, int buf) {
            const uint32_t b0 = sb + buf * STG_STRIDE;
            const int kt = kti * KT;
#pragma unroll
            for (int i = 0; i < 4; i++) {               // A: 1024 chunks
                int chunk = tid + i * 256;
                int row = chunk >> 3, c16 = chunk & 7;
                long g = (long)(m0 + row) * lda + kt + c16 * 8;
                uint32_t so = SWZ((uint32_t)(row * 128 + c16 * 16));
                cp16(b0 + OFF_AH + so, Ah + g);
                cp16(b0 + OFF_AL + so, Al + g);
            }
#pragma unroll
            for (int i = 0; i < 2; i++) {               // B: 512 chunks
                int chunk = tid + i * 256;
                int row = chunk >> 3, c16 = chunk & 7;
                long g = (long)(n0 + row) * ldb + kt + c16 * 8;
                uint32_t so = SWZ((uint32_t)(row * 128 + c16 * 16));
                cp16(b0 + OFF_BH + so, Bh + g);
                cp16(b0 + OFF_BL + so, Bl + g);
            }
        };
        stage(0, 0);
        CP_COMMIT();
        for (int t = 0; t < ntiles; t++) {
            if (t + 1 < ntiles) { stage(t + 1, (t + 1) & 1); CP_COMMIT(); CP_WAIT1(); }
            else { CP_WAIT0(); }
            __syncthreads();
            const uint32_t b0 = sb + (t & 1) * STG_STRIDE;
#pragma unroll
            for (int ks = 0; ks < 4; ks++) {
                const uint32_t kb = ks * 32 + lkh * 16;
                uint32_t ah[2][4], al[2][4];
#pragma unroll
                for (int ms = 0; ms < 2; ms++) {
                    uint32_t ro = (uint32_t)(wm * 32 + ms * 16 + lrow) * 128 + kb;
                    ldsm_x4(ah[ms][0], ah[ms][1], ah[ms][2], ah[ms][3], b0 + OFF_AH + SWZ(ro));
                    ldsm_x4(al[ms][0], al[ms][1], al[ms][2], al[ms][3], b0 + OFF_AL + SWZ(ro));
                }
                uint32_t bh[4][2], bl[4][2];
#pragma unroll
                for (int half = 0; half < 2; half++) {
                    uint32_t ro = (uint32_t)(wn * 32 + half * 16 + lrow) * 128 + kb;
                    uint32_t r0, r1, r2, r3;
                    ldsm_x4(r0, r1, r2, r3, b0 + OFF_BH + SWZ(ro));
                    bh[half * 2 + 0][0] = r0; bh[half * 2 + 0][1] = r2;
                    bh[half * 2 + 1][0] = r1; bh[half * 2 + 1][1] = r3;
                    ldsm_x4(r0, r1, r2, r3, b0 + OFF_BL + SWZ(ro));
                    bl[half * 2 + 0][0] = r0; bl[half * 2 + 0][1] = r2;
                    bl[half * 2 + 1][0] = r1; bl[half * 2 + 1][1] = r3;
                }
#pragma unroll
                for (int ms = 0; ms < 2; ms++)
#pragma unroll
                    for (int nb = 0; nb < 4; nb++) {
                        mma16816(acc[ms][nb], ah[ms], bh[nb][0], bh[nb][1]);
                        mma16816(acc[ms][nb], al[ms], bh[nb][0], bh[nb][1]);
                        mma16816(acc[ms][nb], ah[ms], bl[nb][0], bl[nb][1]);
                    }
            }
            __syncthreads();
        }
    } else {
        // ---------------- synchronous mainloop (fp32 A, split in-kernel) ---
        for (int kt = 0; kt < K; kt += KT) {
            if (kt) __syncthreads();
#pragma unroll 4
            for (int i = tid; i < MT * KT / 2; i += 256) {
                int row = i >> 5, cp = i & 31;
                float2 f = *(const float2*)(Af + (long)(m0 + row) * lda + kt + cp * 2);
                __nv_bfloat16 h0 = __float2bfloat16(f.x), h1 = __float2bfloat16(f.y);
                __nv_bfloat16 l0 = __float2bfloat16(f.x - __bfloat162float(h0));
                __nv_bfloat16 l1 = __float2bfloat16(f.y - __bfloat162float(h1));
                uint32_t hv = (uint32_t)__bfloat16_as_ushort(h0) |
                              ((uint32_t)__bfloat16_as_ushort(h1) << 16);
                uint32_t lv = (uint32_t)__bfloat16_as_ushort(l0) |
                              ((uint32_t)__bfloat16_as_ushort(l1) << 16);
                uint32_t so = SWZ((uint32_t)(row * 128 + cp * 4));
                *(uint32_t*)(dsm + OFF_AH + so) = hv;
                *(uint32_t*)(dsm + OFF_AL + so) = lv;
            }
#pragma unroll 4
            for (int i = tid; i < NT * KT / 2; i += 256) {
                int row = i >> 5, cp = i & 31;
                long g = (long)(n0 + row) * ldb + kt + cp * 2;
                uint32_t hv = *(const uint32_t*)(Bh + g);
                uint32_t lv = *(const uint32_t*)(Bl + g);
                uint32_t so = SWZ((uint32_t)(row * 128 + cp * 4));
                *(uint32_t*)(dsm + OFF_BH + so) = hv;
                *(uint32_t*)(dsm + OFF_BL + so) = lv;
            }
            __syncthreads();
#pragma unroll
            for (int ks = 0; ks < 4; ks++) {
                const uint32_t kb = ks * 32 + lkh * 16;
                uint32_t ah[2][4], al[2][4];
#pragma unroll
                for (int ms = 0; ms < 2; ms++) {
                    uint32_t ro = (uint32_t)(wm * 32 + ms * 16 + lrow) * 128 + kb;
                    ldsm_x4(ah[ms][0], ah[ms][1], ah[ms][2], ah[ms][3], sb + OFF_AH + SWZ(ro));
                    ldsm_x4(al[ms][0], al[ms][1], al[ms][2], al[ms][3], sb + OFF_AL + SWZ(ro));
                }
                uint32_t bh[4][2], bl[4][2];
#pragma unroll
                for (int half = 0; half < 2; half++) {
                    uint32_t ro = (uint32_t)(wn * 32 + half * 16 + lrow) * 128 + kb;
                    uint32_t r0, r1, r2, r3;
                    ldsm_x4(r0, r1, r2, r3, sb + OFF_BH + SWZ(ro));
                    bh[half * 2 + 0][0] = r0; bh[half * 2 + 0][1] = r2;
                    bh[half * 2 + 1][0] = r1; bh[half * 2 + 1][1] = r3;
                    ldsm_x4(r0, r1, r2, r3, sb + OFF_BL + SWZ(ro));
                    bl[half * 2 + 0][0] = r0; bl[half * 2 + 0][1] = r2;
                    bl[half * 2 + 1][0] = r1; bl[half * 2 + 1][1] = r3;
                }
#pragma unroll
                for (int ms = 0; ms < 2; ms++)
#pragma unroll
                    for (int nb = 0; nb < 4; nb++) {
                        mma16816(acc[ms][nb], ah[ms], bh[nb][0], bh[nb][1]);
                        mma16816(acc[ms][nb], al[ms], bh[nb][0], bh[nb][1]);
                        mma16816(acc[ms][nb], ah[ms], bl[nb][0], bl[nb][1]);
                    }
            }
        }
        __syncthreads();
    }

    // ---- epilogue: regs -> padded smem staging -> coalesced global ----
    float* st = (float*)dsm;                     // [128][65] fp32 (33280 B)
    {
        const int lr = lane >> 2, lc = (lane & 3) * 2;
#pragma unroll
        for (int ms = 0; ms < 2; ms++)
#pragma unroll
            for (int nb = 0; nb < 4; nb++) {
                int r = wm * 32 + ms * 16 + lr;
                int c = wn * 32 + nb * 8 + lc;
                st[r * 65 + c]            = acc[ms][nb][0];
                st[r * 65 + c + 1]        = acc[ms][nb][1];
                st[(r + 8) * 65 + c]      = acc[ms][nb][2];
                st[(r + 8) * 65 + c + 1]  = acc[ms][nb][3];
            }
    }
    __syncthreads();

    if (EPI == 4) {            // OUT: fp32 + bias, ld 1024
        for (int i = tid; i < MT * NT; i += 256) {
            int row = i >> 6, c = i & 63;
            outF[(long)(m0 + row) * 1024 + n0 + c] = st[row * 65 + c] + bias[n0 + c];
        }
    } else if (EPI == 0) {     // LIN: bias + split, ld 1024
        for (int i = tid; i < MT * NT; i += 256) {
            int row = i >> 6, c = i & 63;
            float v = st[row * 65 + c] + bias[n0 + c];
            long o = (long)(m0 + row) * 1024 + n0 + c;
            __nv_bfloat16 h = __float2bfloat16(v);
            outH[o] = h;
            outL[o] = __float2bfloat16(v - __bfloat162float(h));
        }
    } else if (EPI == 1) {     // VT: bias + split, transposed per-head [BH,64,S]
        for (int i = tid; i < MT * NT; i += 256) {
            int j = i >> 7, rl = i & 127;
            int r = m0 + rl, cg = n0 + j;
            float v = st[rl * 65 + j] + bias[cg];
            int b = r >> 11, s = r & 2047, hh = cg >> 6, jj = cg & 63;
            long o = ((long)(b * 16 + hh) * 64 + jj) * 2048 + s;
            __nv_bfloat16 h = __float2bfloat16(v);
            outH[o] = h;
            outL[o] = __float2bfloat16(v - __bfloat162float(h));
        }
    } else {                   // CTX: split, [B,S,D] head-interleave (n0 == 0)
        int b = z >> 4, hh = z & 15;
        for (int i = tid; i < MT * NT; i += 256) {
            int row = i >> 6, c = i & 63;
            float v = st[row * 65 + c];
            long o = (long)((b << 11) + m0 + row) * 1024 + hh * 64 + c;
            __nv_bfloat16 h = __float2bfloat16(v);
            outH[o] = h;
            outL[o] = __float2bfloat16(v - __bfloat162float(h));
        }
    }
}

// ---------------------------------------------------------------------------
// Fused scores + softmax.  Per CTA: one head z, 128 q-rows, all 2048 keys.
// Max-free softmax (scores ~ N(0,1), exp safe in fp32).  Pass A: accumulate
// deterministic per-row sum of exp via quad-shuffle + smem partials.
// Pass B: recompute MMAs, store exp(s/8) * inv_rowsum directly to attn.
// smem: q hi/lo 32KB + k 2-stage hi/lo 32KB + partials/rowsum ~1.5KB.
// ---------------------------------------------------------------------------
#define FA_QH   0
#define FA_QL   16384
#define FA_K0   32768          // k stage buf: hi at +0 (8KB), lo at +8192
#define FA_PART 65536          // float[2][128]
#define FA_ROWL 66560          // float[128]
#define FA_SM   67072

__global__ void __launch_bounds__(256)
fused_attn_k(const __nv_bfloat16* __restrict__ qh, const __nv_bfloat16* __restrict__ ql,
             const __nv_bfloat16* __restrict__ kh, const __nv_bfloat16* __restrict__ kl,
             float* __restrict__ attn)
{
    extern __shared__ uint8_t dsm[];
    const uint32_t sb = smem_u32(dsm);
    const int tid = threadIdx.x, wid = tid >> 5, lane = tid & 31;
    const int wm = wid >> 1, wn = wid & 1;
    const int lrow = lane & 15, lkh = lane >> 4;
    const int lr = lane >> 2, lc = lane & 3;
    const int m0 = blockIdx.x * 128;
    const int z = blockIdx.y;
    const long base = (long)(z >> 4) * 2048L * 1024 + (long)(z & 15) * 64;
    const __nv_bfloat16* qh_h = qh + base;
    const __nv_bfloat16* ql_h = ql + base;
    const __nv_bfloat16* kh_h = kh + base;
    const __nv_bfloat16* kl_h = kl + base;

    float* part  = (float*)(dsm + FA_PART);
    float* row_l = (float*)(dsm + FA_ROWL);

    auto stage_k = [&](int t, int buf) {
        const uint32_t kd = sb + FA_K0 + buf * 16384;
#pragma unroll
        for (int i = 0; i < 2; i++) {
            int chunk = tid + i * 256;               // 512 chunks: 64 rows x 8
            int row = chunk >> 3, c16 = chunk & 7;
            long g = (long)(t * 64 + row) * 1024 + c16 * 8;
            uint32_t so = SWZ((uint32_t)(row * 128 + c16 * 16));
            cp16(kd + so, kh_h + g);
            cp16(kd + 8192 + so, kl_h + g);
        }
    };
    auto compute_tile = [&](int buf, float acc[2][4][4]) {
#pragma unroll
        for (int i = 0; i < 2; i++)
#pragma unroll
            for (int j = 0; j < 4; j++)
#pragma unroll
                for (int r = 0; r < 4; r++) acc[i][j][r] = 0.0f;
        const uint32_t kbh = sb + FA_K0 + buf * 16384;
        const uint32_t kbl = kbh + 8192;
#pragma unroll
        for (int ks = 0; ks < 4; ks++) {
            const uint32_t kb = ks * 32 + lkh * 16;
            uint32_t ah[2][4], al[2][4];
#pragma unroll
            for (int ms = 0; ms < 2; ms++) {
                uint32_t ro = (uint32_t)(wm * 32 + ms * 16 + lrow) * 128 + kb;
                ldsm_x4(ah[ms][0], ah[ms][1], ah[ms][2], ah[ms][3], sb + FA_QH + SWZ(ro));
                ldsm_x4(al[ms][0], al[ms][1], al[ms][2], al[ms][3], sb + FA_QL + SWZ(ro));
            }
            uint32_t bh[4][2], bl[4][2];
#pragma unroll
            for (int half = 0; half < 2; half++) {
                uint32_t ro = (uint32_t)(wn * 32 + half * 16 + lrow) * 128 + kb;
                uint32_t r0, r1, r2, r3;
                ldsm_x4(r0, r1, r2, r3, kbh + SWZ(ro));
                bh[half * 2 + 0][0] = r0; bh[half * 2 + 0][1] = r2;
                bh[half * 2 + 1][0] = r1; bh[half * 2 + 1][1] = r3;
                ldsm_x4(r0, r1, r2, r3, kbl + SWZ(ro));
                bl[half * 2 + 0][0] = r0; bl[half * 2 + 0][1] = r2;
                bl[half * 2 + 1][0] = r1; bl[half * 2 + 1][1] = r3;
            }
#pragma unroll
            for (int ms = 0; ms < 2; ms++)
#pragma unroll
                for (int nb = 0; nb < 4; nb++) {
                    mma16816(acc[ms][nb], ah[ms], bh[nb][0], bh[nb][1]);
                    mma16816(acc[ms][nb], al[ms], bh[nb][0], bh[nb][1]);
                    mma16816(acc[ms][nb], ah[ms], bl[nb][0], bl[nb][1]);
                }
        }
    };

    // ---- prologue: q tile + k tile 0 ----
#pragma unroll
    for (int i = 0; i < 4; i++) {
        int chunk = tid + i * 256;                   // 1024 chunks: 128 rows x 8
        int row = chunk >> 3, c16 = chunk & 7;
        long g = (long)(m0 + row) * 1024 + c16 * 8;
        uint32_t so = SWZ((uint32_t)(row * 128 + c16 * 16));
        cp16(sb + FA_QH + so, qh_h + g);
        cp16(sb + FA_QL + so, ql_h + g);
    }
    if (tid < 128) row_l[tid] = 0.0f;
    stage_k(0, 0);
    CP_COMMIT();

    float acc[2][4][4];

    // ---- pass A: row sums of exp ----
    for (int t = 0; t < 32; t++) {
        if (t + 1 < 32) { stage_k(t + 1, (t + 1) & 1); CP_COMMIT(); CP_WAIT1(); }
        else { CP_WAIT0(); }
        __syncthreads();                              // tile ready; part free
        compute_tile(t & 1, acc);
#pragma unroll
        for (int ms = 0; ms < 2; ms++) {
            float s0 = 0.0f, s1 = 0.0f;
#pragma unroll
            for (int nb = 0; nb < 4; nb++) {
                s0 += __expf(acc[ms][nb][0] * 0.125f) + __expf(acc[ms][nb][1] * 0.125f);
                s1 += __expf(acc[ms][nb][2] * 0.125f) + __expf(acc[ms][nb][3] * 0.125f);
            }
            s0 += __shfl_xor_sync(0xffffffffu, s0, 1);
            s0 += __shfl_xor_sync(0xffffffffu, s0, 2);
            s1 += __shfl_xor_sync(0xffffffffu, s1, 1);
            s1 += __shfl_xor_sync(0xffffffffu, s1, 2);
            if (lc == 0) {
                part[wn * 128 + wm * 32 + ms * 16 + lr]     = s0;
                part[wn * 128 + wm * 32 + ms * 16 + 8 + lr] = s1;
            }
        }
        __syncthreads();                              // partials visible
        if (tid < 128) row_l[tid] += part[tid] + part[128 + tid];
    }
    __syncthreads();
    float inv[2][2];
#pragma unroll
    for (int ms = 0; ms < 2; ms++) {
        inv[ms][0] = 1.0f / row_l[wm * 32 + ms * 16 + lr];
        inv[ms][1] = 1.0f / row_l[wm * 32 + ms * 16 + 8 + lr];
    }

    // ---- pass B: recompute and store normalized attn ----
    stage_k(0, 0);
    CP_COMMIT();
    for (int t = 0; t < 32; t++) {
        if (t + 1 < 32) { stage_k(t + 1, (t + 1) & 1); CP_COMMIT(); CP_WAIT1(); }
        else { CP_WAIT0(); }
        __syncthreads();
        compute_tile(t & 1, acc);
        const int colb = t * 64 + wn * 32 + lc * 2;
#pragma unroll
        for (int ms = 0; ms < 2; ms++) {
            long rb0 = ((long)z * 2048 + m0 + wm * 32 + ms * 16 + lr) * 2048;
            long rb1 = rb0 + 8L * 2048;
#pragma unroll
            for (int nb = 0; nb < 4; nb++) {
                float2 v0 = make_float2(__expf(acc[ms][nb][0] * 0.125f) * inv[ms][0],
                                        __expf(acc[ms][nb][1] * 0.125f) * inv[ms][0]);
                float2 v1 = make_float2(__expf(acc[ms][nb][2] * 0.125f) * inv[ms][1],
                                        __expf(acc[ms][nb][3] * 0.125f) * inv[ms][1]);
                *(float2*)(attn + rb0 + colb + nb * 8) = v0;
                *(float2*)(attn + rb1 + colb + nb * 8) = v1;
            }
        }
        __syncthreads();                              // buffer reuse guard
    }
}

// ---------------------------------------------------------------------------
extern "C" void kernel_launch(void* const* d_in, const int* in_sizes, int n_in,
                              void* d_out, int out_size)
{
    const float* Q  = (const float*)d_in[0];
    const float* K  = (const float*)d_in[1];
    const float* V  = (const float*)d_in[2];
    const float* Wq = (const float*)d_in[3];
    const float* bq = (const float*)d_in[4];
    const float* Wk = (const float*)d_in[5];
    const float* bk = (const float*)d_in[6];
    const float* Wv = (const float*)d_in[7];
    const float* bv = (const float*)d_in[8];
    const float* Wo = (const float*)d_in[9];
    const float* bo = (const float*)d_in[10];
    float* out = (float*)d_out;

    __nv_bfloat16 *Qh, *Ql, *Kh, *Kl, *Vh, *Vl;
    __nv_bfloat16 *Wqh, *Wql, *Wkh, *Wkl, *Wvh, *Wvl, *Woh, *Wol;
    __nv_bfloat16 *qh, *ql, *kh, *kl, *vth, *vtl, *ch, *cl;
    float* attn_scratch;
    cudaGetSymbolAddress((void**)&Qh, g_Qh);   cudaGetSymbolAddress((void**)&Ql, g_Ql);
    cudaGetSymbolAddress((void**)&Kh, g_Kh);   cudaGetSymbolAddress((void**)&Kl, g_Kl);
    cudaGetSymbolAddress((void**)&Vh, g_Vh);   cudaGetSymbolAddress((void**)&Vl, g_Vl);
    cudaGetSymbolAddress((void**)&Wqh, g_Wqh); cudaGetSymbolAddress((void**)&Wql, g_Wql);
    cudaGetSymbolAddress((void**)&Wkh, g_Wkh); cudaGetSymbolAddress((void**)&Wkl, g_Wkl);
    cudaGetSymbolAddress((void**)&Wvh, g_Wvh); cudaGetSymbolAddress((void**)&Wvl, g_Wvl);
    cudaGetSymbolAddress((void**)&Woh, g_Woh); cudaGetSymbolAddress((void**)&Wol, g_Wol);
    cudaGetSymbolAddress((void**)&qh, g_qh);   cudaGetSymbolAddress((void**)&ql, g_ql);
    cudaGetSymbolAddress((void**)&kh, g_kh);   cudaGetSymbolAddress((void**)&kl, g_kl);
    cudaGetSymbolAddress((void**)&vth, g_vth); cudaGetSymbolAddress((void**)&vtl, g_vtl);
    cudaGetSymbolAddress((void**)&ch, g_ch);   cudaGetSymbolAddress((void**)&cl, g_cl);
    cudaGetSymbolAddress((void**)&attn_scratch, g_attn);

    float* attn = ((long)out_size >= OUT_TOTAL) ? (out + OUT0) : attn_scratch;

    cudaFuncSetAttribute(mma_gemm<0, 0>, cudaFuncAttributeMaxDynamicSharedMemorySize, SM_PIPE);
    cudaFuncSetAttribute(mma_gemm<0, 1>, cudaFuncAttributeMaxDynamicSharedMemorySize, SM_PIPE);
    cudaFuncSetAttribute(mma_gemm<1, 3>, cudaFuncAttributeMaxDynamicSharedMemorySize, SM_SYNC);
    cudaFuncSetAttribute(mma_gemm<0, 4>, cudaFuncAttributeMaxDynamicSharedMemorySize, SM_PIPE);
    cudaFuncSetAttribute(fused_attn_k,   cudaFuncAttributeMaxDynamicSharedMemorySize, FA_SM);

    // 0) Split all GEMM inputs to bf16 hi/lo
    const int NI = TOKENS * DMODEL, NW = DMODEL * DMODEL;
    split_k<<<NI / 256, 256>>>(Q, Qh, Ql, NI);
    split_k<<<NI / 256, 256>>>(K, Kh, Kl, NI);
    split_k<<<NI / 256, 256>>>(V, Vh, Vl, NI);
    split_k<<<NW / 256, 256>>>(Wq, Wqh, Wql, NW);
    split_k<<<NW / 256, 256>>>(Wk, Wkh, Wkl, NW);
    split_k<<<NW / 256, 256>>>(Wv, Wvh, Wvl, NW);
    split_k<<<NW / 256, 256>>>(Wo, Woh, Wol, NW);

    // 1-3) Projections: [4096,1024] @ W^T + b (pipelined)
    dim3 gp(DMODEL / NT, TOKENS / MT, 1);                       // (16, 32)
    mma_gemm<0, 0><<<gp, 256, SM_PIPE>>>(Qh, Ql, Wqh, Wql, bq, nullptr, qh, ql,
                                         DMODEL, DMODEL, DMODEL);
    mma_gemm<0, 0><<<gp, 256, SM_PIPE>>>(Kh, Kl, Wkh, Wkl, bk, nullptr, kh, kl,
                                         DMODEL, DMODEL, DMODEL);
    mma_gemm<0, 1><<<gp, 256, SM_PIPE>>>(Vh, Vl, Wvh, Wvl, bv, nullptr, vth, vtl,
                                         DMODEL, DMODEL, DMODEL);

    // 4) Fused scores + softmax -> attn (written exactly once)
    dim3 gf(SEQ / 128, BH, 1);                                  // (16, 32)
    fused_attn_k<<<gf, 256, FA_SM>>>(qh, ql, kh, kl, attn);

    // 5) Context: per head, attn[2048,2048] @ vt[64,2048]^T -> ctx splits
    dim3 gc(1, SEQ / MT, BH);                                   // (1, 16, 32)
    mma_gemm<1, 3><<<gc, 256, SM_SYNC>>>(attn, nullptr, vth, vtl, nullptr, nullptr,
                                         ch, cl, SEQ, SEQ, SEQ);

    // 6) Output projection: ctx @ Wo^T + bo -> out fp32 (pipelined)
    mma_gemm<0, 4><<<gp, 256, SM_PIPE>>>(ch, cl, Woh, Wol, bo, out, nullptr, nullptr,
                                         DMODEL, DMODEL, DMODEL);

    (void)n_in; (void)in_sizes;
}

// round 7
// speedup vs baseline: 3.6010x; 1.1210x over previous
#include <cuda_runtime.h>
#include <cuda_bf16.h>
#include <cstdint>

// ---------------------------------------------------------------------------
// Problem constants
// ---------------------------------------------------------------------------
#define BATCH   2
#define SEQ     2048
#define DMODEL  1024
#define NHEAD   16
#define DK      64
#define BH      (BATCH * NHEAD)              // 32
#define TOKENS  (BATCH * SEQ)                // 4096
#define OUT0    (TOKENS * DMODEL)            // 4,194,304
#define ATTN_N  ((long)BH * SEQ * SEQ)       // 134,217,728
#define OUT_TOTAL (OUT0 + ATTN_N)

// ---------------------------------------------------------------------------
// Scratch (static device arrays; no cudaMalloc anywhere)
// ---------------------------------------------------------------------------
__device__ __nv_bfloat16 g_Qh[TOKENS * DMODEL], g_Ql[TOKENS * DMODEL];
__device__ __nv_bfloat16 g_Kh[TOKENS * DMODEL], g_Kl[TOKENS * DMODEL];
__device__ __nv_bfloat16 g_Vh[TOKENS * DMODEL], g_Vl[TOKENS * DMODEL];
__device__ __nv_bfloat16 g_Wqh[DMODEL * DMODEL], g_Wql[DMODEL * DMODEL];
__device__ __nv_bfloat16 g_Wkh[DMODEL * DMODEL], g_Wkl[DMODEL * DMODEL];
__device__ __nv_bfloat16 g_Wvh[DMODEL * DMODEL], g_Wvl[DMODEL * DMODEL];
__device__ __nv_bfloat16 g_Woh[DMODEL * DMODEL], g_Wol[DMODEL * DMODEL];
__device__ __nv_bfloat16 g_qh[TOKENS * DMODEL], g_ql[TOKENS * DMODEL];   // [B,S,H*64]
__device__ __nv_bfloat16 g_kh[TOKENS * DMODEL], g_kl[TOKENS * DMODEL];   // [B,S,H*64]
__device__ __nv_bfloat16 g_vth[BH * DK * SEQ], g_vtl[BH * DK * SEQ];     // [BH,64,S]
__device__ __nv_bfloat16 g_ch[TOKENS * DMODEL], g_cl[TOKENS * DMODEL];   // ctx [B,S,D]
__device__ float g_attn[ATTN_N];                 // fallback if d_out lacks attn

// ---------------------------------------------------------------------------
// Helpers
// ---------------------------------------------------------------------------
__device__ __forceinline__ uint32_t smem_u32(const void* p) {
    uint32_t a;
    asm("{ .reg .u64 t; cvta.to.shared.u64 t, %1; cvt.u32.u64 %0, t; }"
        : "=r"(a) : "l"(p));
    return a;
}
#define SWZ(off) ((off) ^ (((off) >> 3) & 0x70))

__device__ __forceinline__ void ldsm_x4(uint32_t& r0, uint32_t& r1,
                                        uint32_t& r2, uint32_t& r3, uint32_t a) {
    asm volatile("ldmatrix.sync.aligned.m8n8.x4.shared.b16 {%0,%1,%2,%3}, [%4];"
                 : "=r"(r0), "=r"(r1), "=r"(r2), "=r"(r3) : "r"(a));
}
__device__ __forceinline__ void mma16816(float* c, const uint32_t* a,
                                         uint32_t b0, uint32_t b1) {
    asm volatile(
        "mma.sync.aligned.m16n8k16.row.col.f32.bf16.bf16.f32 "
        "{%0,%1,%2,%3}, {%4,%5,%6,%7}, {%8,%9}, {%0,%1,%2,%3};"
        : "+f"(c[0]), "+f"(c[1]), "+f"(c[2]), "+f"(c[3])
        : "r"(a[0]), "r"(a[1]), "r"(a[2]), "r"(a[3]), "r"(b0), "r"(b1));
}
__device__ __forceinline__ void cp16(uint32_t dst, const void* src) {
    asm volatile("cp.async.cg.shared.global [%0], [%1], 16;"
                 :: "r"(dst), "l"(src) : "memory");
}
#define CP_COMMIT() asm volatile("cp.async.commit_group;" ::: "memory")
#define CP_WAIT1()  asm volatile("cp.async.wait_group 1;" ::: "memory")
#define CP_WAIT0()  asm volatile("cp.async.wait_group 0;" ::: "memory")

// pack two fp32 -> bf16x2 register (lo in low half)
__device__ __forceinline__ uint32_t pack_bf16(float lo, float hi) {
    uint32_t r;
    asm("cvt.rn.bf16x2.f32 %0, %1, %2;" : "=r"(r) : "f"(hi), "f"(lo));
    return r;
}
__device__ __forceinline__ float bf16lo_f(uint32_t r) {
    return __bfloat162float(__ushort_as_bfloat16((unsigned short)(r & 0xffffu)));
}
__device__ __forceinline__ float bf16hi_f(uint32_t r) {
    return __bfloat162float(__ushort_as_bfloat16((unsigned short)(r >> 16)));
}

// ---------------------------------------------------------------------------
// fp32 -> bf16 hi/lo split (pre-pass for GEMM inputs)
// ---------------------------------------------------------------------------
__global__ void __launch_bounds__(256)
split_k(const float* __restrict__ x, __nv_bfloat16* __restrict__ h,
        __nv_bfloat16* __restrict__ l, int n)
{
    int i = blockIdx.x * 256 + threadIdx.x;
    if (i < n) {
        float v = x[i];
        __nv_bfloat16 hv = __float2bfloat16(v);
        h[i] = hv;
        l[i] = __float2bfloat16(v - __bfloat162float(hv));
    }
}

// ---------------------------------------------------------------------------
// mma.sync split-bf16 GEMM (pre-split bf16 operands, cp.async 2-stage).
// Tile M=128, N=64, K-tile=64; 256 threads (8 warps, 4x2 grid, 32x32/warp).
// C = A @ B^T, K-major SW128 smem tiles.  3 HMMA passes per fragment.
// EPI:  0 LIN (bias + split store, ld 1024)            [Q/K projections]
//       1 VT  (bias + split store transposed per-head) [V projection]
//       4 OUT (bias, fp32 store ld 1024)               [output projection]
// ---------------------------------------------------------------------------
#define MT 128
#define NT 64
#define KT 64
#define STG_STRIDE 49152
#define OFF_AH 0
#define OFF_AL 16384
#define OFF_BH 32768
#define OFF_BL 40960
#define SM_PIPE  98304

template <int EPI>
__global__ void __launch_bounds__(256)
mma_gemm(const __nv_bfloat16* __restrict__ Ah, const __nv_bfloat16* __restrict__ Al,
         const __nv_bfloat16* __restrict__ Bh, const __nv_bfloat16* __restrict__ Bl,
         const float* __restrict__ bias, float* __restrict__ outF,
         __nv_bfloat16* __restrict__ outH, __nv_bfloat16* __restrict__ outL,
         int K, int lda, int ldb)
{
    extern __shared__ uint8_t dsm[];
    const uint32_t sb = smem_u32(dsm);
    const int tid = threadIdx.x, wid = tid >> 5, lane = tid & 31;
    const int wm = wid >> 1, wn = wid & 1;
    const int n0 = blockIdx.x * NT, m0 = blockIdx.y * MT;

    float acc[2][4][4];
#pragma unroll
    for (int i = 0; i < 2; i++)
#pragma unroll
        for (int j = 0; j < 4; j++)
#pragma unroll
            for (int r = 0; r < 4; r++) acc[i][j][r] = 0.0f;

    const int lrow = lane & 15, lkh = lane >> 4;

    const int ntiles = K / KT;
    auto stage = [&](int kti, int buf) {
        const uint32_t b0 = sb + buf * STG_STRIDE;
        const int kt = kti * KT;
#pragma unroll
        for (int i = 0; i < 4; i++) {
            int chunk = tid + i * 256;
            int row = chunk >> 3, c16 = chunk & 7;
            long g = (long)(m0 + row) * lda + kt + c16 * 8;
            uint32_t so = SWZ((uint32_t)(row * 128 + c16 * 16));
            cp16(b0 + OFF_AH + so, Ah + g);
            cp16(b0 + OFF_AL + so, Al + g);
        }
#pragma unroll
        for (int i = 0; i < 2; i++) {
            int chunk = tid + i * 256;
            int row = chunk >> 3, c16 = chunk & 7;
            long g = (long)(n0 + row) * ldb + kt + c16 * 8;
            uint32_t so = SWZ((uint32_t)(row * 128 + c16 * 16));
            cp16(b0 + OFF_BH + so, Bh + g);
            cp16(b0 + OFF_BL + so, Bl + g);
        }
    };
    stage(0, 0);
    CP_COMMIT();
    for (int t = 0; t < ntiles; t++) {
        if (t + 1 < ntiles) { stage(t + 1, (t + 1) & 1); CP_COMMIT(); CP_WAIT1(); }
        else { CP_WAIT0(); }
        __syncthreads();
        const uint32_t b0 = sb + (t & 1) * STG_STRIDE;
#pragma unroll
        for (int ks = 0; ks < 4; ks++) {
            const uint32_t kb = ks * 32 + lkh * 16;
            uint32_t ah[2][4], al[2][4];
#pragma unroll
            for (int ms = 0; ms < 2; ms++) {
                uint32_t ro = (uint32_t)(wm * 32 + ms * 16 + lrow) * 128 + kb;
                ldsm_x4(ah[ms][0], ah[ms][1], ah[ms][2], ah[ms][3], b0 + OFF_AH + SWZ(ro));
                ldsm_x4(al[ms][0], al[ms][1], al[ms][2], al[ms][3], b0 + OFF_AL + SWZ(ro));
            }
            uint32_t bh[4][2], bl[4][2];
#pragma unroll
            for (int half = 0; half < 2; half++) {
                uint32_t ro = (uint32_t)(wn * 32 + half * 16 + lrow) * 128 + kb;
                uint32_t r0, r1, r2, r3;
                ldsm_x4(r0, r1, r2, r3, b0 + OFF_BH + SWZ(ro));
                bh[half * 2 + 0][0] = r0; bh[half * 2 + 0][1] = r2;
                bh[half * 2 + 1][0] = r1; bh[half * 2 + 1][1] = r3;
                ldsm_x4(r0, r1, r2, r3, b0 + OFF_BL + SWZ(ro));
                bl[half * 2 + 0][0] = r0; bl[half * 2 + 0][1] = r2;
                bl[half * 2 + 1][0] = r1; bl[half * 2 + 1][1] = r3;
            }
#pragma unroll
            for (int ms = 0; ms < 2; ms++)
#pragma unroll
                for (int nb = 0; nb < 4; nb++) {
                    mma16816(acc[ms][nb], ah[ms], bh[nb][0], bh[nb][1]);
                    mma16816(acc[ms][nb], al[ms], bh[nb][0], bh[nb][1]);
                    mma16816(acc[ms][nb], ah[ms], bl[nb][0], bl[nb][1]);
                }
        }
        __syncthreads();
    }

    // ---- epilogue: regs -> padded smem staging -> coalesced global ----
    float* st = (float*)dsm;                     // [128][65] fp32
    {
        const int lr = lane >> 2, lc = (lane & 3) * 2;
#pragma unroll
        for (int ms = 0; ms < 2; ms++)
#pragma unroll
            for (int nb = 0; nb < 4; nb++) {
                int r = wm * 32 + ms * 16 + lr;
                int c = wn * 32 + nb * 8 + lc;
                st[r * 65 + c]            = acc[ms][nb][0];
                st[r * 65 + c + 1]        = acc[ms][nb][1];
                st[(r + 8) * 65 + c]      = acc[ms][nb][2];
                st[(r + 8) * 65 + c + 1]  = acc[ms][nb][3];
            }
    }
    __syncthreads();

    if (EPI == 4) {            // OUT: fp32 + bias, ld 1024
        for (int i = tid; i < MT * NT; i += 256) {
            int row = i >> 6, c = i & 63;
            outF[(long)(m0 + row) * 1024 + n0 + c] = st[row * 65 + c] + bias[n0 + c];
        }
    } else if (EPI == 0) {     // LIN: bias + split, ld 1024
        for (int i = tid; i < MT * NT; i += 256) {
            int row = i >> 6, c = i & 63;
            float v = st[row * 65 + c] + bias[n0 + c];
            long o = (long)(m0 + row) * 1024 + n0 + c;
            __nv_bfloat16 h = __float2bfloat16(v);
            outH[o] = h;
            outL[o] = __float2bfloat16(v - __bfloat162float(h));
        }
    } else {                   // VT: bias + split, transposed per-head [BH,64,S]
        for (int i = tid; i < MT * NT; i += 256) {
            int j = i >> 7, rl = i & 127;
            int r = m0 + rl, cg = n0 + j;
            float v = st[rl * 65 + j] + bias[cg];
            int b = r >> 11, s = r & 2047, hh = cg >> 6, jj = cg & 63;
            long o = ((long)(b * 16 + hh) * 64 + jj) * 2048 + s;
            __nv_bfloat16 h = __float2bfloat16(v);
            outH[o] = h;
            outL[o] = __float2bfloat16(v - __bfloat162float(h));
        }
    }
}

// ---------------------------------------------------------------------------
// Fused scores + softmax + context.  Per CTA: head z, 128 q-rows, 2048 keys.
// Pass A: S tiles -> deterministic per-row sum of exp.
// Pass B: recompute S, normalize P, store attn (only HBM touch), split P to
//         bf16 hi/lo in registers, accumulate O += P @ V^T (3-pass split),
//         cross-wn reduce in smem, store ctx hi/lo.
// ---------------------------------------------------------------------------
#define FB_QH   0
#define FB_QL   16384
#define FB_ST0  32768           // per stage: KH+0, KL+8192, VH+16384, VL+24576
#define FB_STRIDE 32768
#define FB_PART 98304           // float[2][128]
#define FB_ROWL 99328           // float[128]
#define FB_SM   99840

__global__ void __launch_bounds__(256)
fused_attn_k(const __nv_bfloat16* __restrict__ qh, const __nv_bfloat16* __restrict__ ql,
             const __nv_bfloat16* __restrict__ kh, const __nv_bfloat16* __restrict__ kl,
             const __nv_bfloat16* __restrict__ vth, const __nv_bfloat16* __restrict__ vtl,
             float* __restrict__ attn,
             __nv_bfloat16* __restrict__ ch, __nv_bfloat16* __restrict__ cl)
{
    extern __shared__ uint8_t dsm[];
    const uint32_t sb = smem_u32(dsm);
    const int tid = threadIdx.x, wid = tid >> 5, lane = tid & 31;
    const int wm = wid >> 1, wn = wid & 1;
    const int lrow = lane & 15, lkh = lane >> 4;
    const int lr = lane >> 2, lc = lane & 3;
    const int m0 = blockIdx.x * 128;
    const int z = blockIdx.y;
    const long base = (long)(z >> 4) * 2048L * 1024 + (long)(z & 15) * 64;
    const __nv_bfloat16* qh_h = qh + base;
    const __nv_bfloat16* ql_h = ql + base;
    const __nv_bfloat16* kh_h = kh + base;
    const __nv_bfloat16* kl_h = kl + base;
    const __nv_bfloat16* vh_h = vth + (long)z * 64L * 2048;
    const __nv_bfloat16* vl_h = vtl + (long)z * 64L * 2048;

    float* part  = (float*)(dsm + FB_PART);
    float* row_l = (float*)(dsm + FB_ROWL);

    auto stage_kv = [&](int t, int buf, bool withV) {
        const uint32_t sd = sb + FB_ST0 + buf * FB_STRIDE;
#pragma unroll
        for (int i = 0; i < 2; i++) {
            int chunk = tid + i * 256;               // 512: 64 rows x 8 chunks
            int row = chunk >> 3, c16 = chunk & 7;
            long g = (long)(t * 64 + row) * 1024 + c16 * 8;
            uint32_t so = SWZ((uint32_t)(row * 128 + c16 * 16));
            cp16(sd + so, kh_h + g);
            cp16(sd + 8192 + so, kl_h + g);
        }
        if (withV) {
#pragma unroll
            for (int i = 0; i < 2; i++) {
                int chunk = tid + i * 256;           // row = dk 0..63
                int row = chunk >> 3, c16 = chunk & 7;
                long g = (long)row * 2048 + t * 64 + c16 * 8;
                uint32_t so = SWZ((uint32_t)(row * 128 + c16 * 16));
                cp16(sd + 16384 + so, vh_h + g);
                cp16(sd + 24576 + so, vl_h + g);
            }
        }
    };
    auto compute_tile = [&](int buf, float acc[2][4][4]) {
#pragma unroll
        for (int i = 0; i < 2; i++)
#pragma unroll
            for (int j = 0; j < 4; j++)
#pragma unroll
                for (int r = 0; r < 4; r++) acc[i][j][r] = 0.0f;
        const uint32_t kbh = sb + FB_ST0 + buf * FB_STRIDE;
        const uint32_t kbl = kbh + 8192;
#pragma unroll
        for (int ks = 0; ks < 4; ks++) {
            const uint32_t kb = ks * 32 + lkh * 16;
            uint32_t ah[2][4], al[2][4];
#pragma unroll
            for (int ms = 0; ms < 2; ms++) {
                uint32_t ro = (uint32_t)(wm * 32 + ms * 16 + lrow) * 128 + kb;
                ldsm_x4(ah[ms][0], ah[ms][1], ah[ms][2], ah[ms][3], sb + FB_QH + SWZ(ro));
                ldsm_x4(al[ms][0], al[ms][1], al[ms][2], al[ms][3], sb + FB_QL + SWZ(ro));
            }
            uint32_t bh[4][2], bl[4][2];
#pragma unroll
            for (int half = 0; half < 2; half++) {
                uint32_t ro = (uint32_t)(wn * 32 + half * 16 + lrow) * 128 + kb;
                uint32_t r0, r1, r2, r3;
                ldsm_x4(r0, r1, r2, r3, kbh + SWZ(ro));
                bh[half * 2 + 0][0] = r0; bh[half * 2 + 0][1] = r2;
                bh[half * 2 + 1][0] = r1; bh[half * 2 + 1][1] = r3;
                ldsm_x4(r0, r1, r2, r3, kbl + SWZ(ro));
                bl[half * 2 + 0][0] = r0; bl[half * 2 + 0][1] = r2;
                bl[half * 2 + 1][0] = r1; bl[half * 2 + 1][1] = r3;
            }
#pragma unroll
            for (int ms = 0; ms < 2; ms++)
#pragma unroll
                for (int nb = 0; nb < 4; nb++) {
                    mma16816(acc[ms][nb], ah[ms], bh[nb][0], bh[nb][1]);
                    mma16816(acc[ms][nb], al[ms], bh[nb][0], bh[nb][1]);
                    mma16816(acc[ms][nb], ah[ms], bl[nb][0], bl[nb][1]);
                }
        }
    };

    // ---- prologue: q tile + k tile 0 ----
#pragma unroll
    for (int i = 0; i < 4; i++) {
        int chunk = tid + i * 256;                   // 1024: 128 rows x 8
        int row = chunk >> 3, c16 = chunk & 7;
        long g = (long)(m0 + row) * 1024 + c16 * 8;
        uint32_t so = SWZ((uint32_t)(row * 128 + c16 * 16));
        cp16(sb + FB_QH + so, qh_h + g);
        cp16(sb + FB_QL + so, ql_h + g);
    }
    if (tid < 128) row_l[tid] = 0.0f;
    stage_kv(0, 0, false);
    CP_COMMIT();

    float acc[2][4][4];

    // ---- pass A: row sums of exp ----
    for (int t = 0; t < 32; t++) {
        if (t + 1 < 32) { stage_kv(t + 1, (t + 1) & 1, false); CP_COMMIT(); CP_WAIT1(); }
        else { CP_WAIT0(); }
        __syncthreads();
        compute_tile(t & 1, acc);
#pragma unroll
        for (int ms = 0; ms < 2; ms++) {
            float s0 = 0.0f, s1 = 0.0f;
#pragma unroll
            for (int nb = 0; nb < 4; nb++) {
                s0 += __expf(acc[ms][nb][0] * 0.125f) + __expf(acc[ms][nb][1] * 0.125f);
                s1 += __expf(acc[ms][nb][2] * 0.125f) + __expf(acc[ms][nb][3] * 0.125f);
            }
            s0 += __shfl_xor_sync(0xffffffffu, s0, 1);
            s0 += __shfl_xor_sync(0xffffffffu, s0, 2);
            s1 += __shfl_xor_sync(0xffffffffu, s1, 1);
            s1 += __shfl_xor_sync(0xffffffffu, s1, 2);
            if (lc == 0) {
                part[wn * 128 + wm * 32 + ms * 16 + lr]     = s0;
                part[wn * 128 + wm * 32 + ms * 16 + 8 + lr] = s1;
            }
        }
        __syncthreads();
        if (tid < 128) row_l[tid] += part[tid] + part[128 + tid];
    }
    __syncthreads();
    float inv[2][2];
#pragma unroll
    for (int ms = 0; ms < 2; ms++) {
        inv[ms][0] = 1.0f / row_l[wm * 32 + ms * 16 + lr];
        inv[ms][1] = 1.0f / row_l[wm * 32 + ms * 16 + 8 + lr];
    }

    // O accumulator: rows 32 (ms 2x16) x dk 64 (dn 8x8) per warp (partial in keys)
    float accO[2][8][4];
#pragma unroll
    for (int ms = 0; ms < 2; ms++)
#pragma unroll
        for (int dn = 0; dn < 8; dn++)
#pragma unroll
            for (int r = 0; r < 4; r++) accO[ms][dn][r] = 0.0f;

    // ---- pass B: recompute, store normalized attn, accumulate O = P @ V^T ----
    stage_kv(0, 0, true);
    CP_COMMIT();
    for (int t = 0; t < 32; t++) {
        if (t + 1 < 32) { stage_kv(t + 1, (t + 1) & 1, true); CP_COMMIT(); CP_WAIT1(); }
        else { CP_WAIT0(); }
        __syncthreads();
        compute_tile(t & 1, acc);

        // normalize in place
#pragma unroll
        for (int ms = 0; ms < 2; ms++)
#pragma unroll
            for (int nb = 0; nb < 4; nb++) {
                acc[ms][nb][0] = __expf(acc[ms][nb][0] * 0.125f) * inv[ms][0];
                acc[ms][nb][1] = __expf(acc[ms][nb][1] * 0.125f) * inv[ms][0];
                acc[ms][nb][2] = __expf(acc[ms][nb][2] * 0.125f) * inv[ms][1];
                acc[ms][nb][3] = __expf(acc[ms][nb][3] * 0.125f) * inv[ms][1];
            }

        // store attn (required output, written exactly once)
        const int colb = t * 64 + wn * 32 + lc * 2;
#pragma unroll
        for (int ms = 0; ms < 2; ms++) {
            long rb0 = ((long)z * 2048 + m0 + wm * 32 + ms * 16 + lr) * 2048;
            long rb1 = rb0 + 8L * 2048;
#pragma unroll
            for (int nb = 0; nb < 4; nb++) {
                *(float2*)(attn + rb0 + colb + nb * 8) =
                    make_float2(acc[ms][nb][0], acc[ms][nb][1]);
                *(float2*)(attn + rb1 + colb + nb * 8) =
                    make_float2(acc[ms][nb][2], acc[ms][nb][3]);
            }
        }

        // O += P @ V^T  (warp handles its 32-key slice; V frags from smem)
        const uint32_t vbh = sb + FB_ST0 + (t & 1) * FB_STRIDE + 16384;
        const uint32_t vbl = vbh + 8192;
#pragma unroll
        for (int kh2 = 0; kh2 < 2; kh2++) {
            uint32_t vh[8][2], vl[8][2];
#pragma unroll
            for (int dh = 0; dh < 4; dh++) {
                // rows = dk dims; byte col = key*2 within tile; lkh selects
                // the key 8..15 half (the missing term that broke R6).
                uint32_t ro = (uint32_t)(dh * 16 + lrow) * 128 +
                              (uint32_t)(wn * 32 + kh2 * 16) * 2 + lkh * 16;
                uint32_t r0, r1, r2, r3;
                ldsm_x4(r0, r1, r2, r3, vbh + SWZ(ro));
                vh[dh * 2 + 0][0] = r0; vh[dh * 2 + 0][1] = r2;
                vh[dh * 2 + 1][0] = r1; vh[dh * 2 + 1][1] = r3;
                ldsm_x4(r0, r1, r2, r3, vbl + SWZ(ro));
                vl[dh * 2 + 0][0] = r0; vl[dh * 2 + 0][1] = r2;
                vl[dh * 2 + 1][0] = r1; vl[dh * 2 + 1][1] = r3;
            }
#pragma unroll
            for (int ms = 0; ms < 2; ms++) {
                const float* c0 = acc[ms][2 * kh2];
                const float* c1 = acc[ms][2 * kh2 + 1];
                uint32_t ph[4], pl[4];
                ph[0] = pack_bf16(c0[0], c0[1]);
                ph[1] = pack_bf16(c0[2], c0[3]);
                ph[2] = pack_bf16(c1[0], c1[1]);
                ph[3] = pack_bf16(c1[2], c1[3]);
                pl[0] = pack_bf16(c0[0] - bf16lo_f(ph[0]), c0[1] - bf16hi_f(ph[0]));
                pl[1] = pack_bf16(c0[2] - bf16lo_f(ph[1]), c0[3] - bf16hi_f(ph[1]));
                pl[2] = pack_bf16(c1[0] - bf16lo_f(ph[2]), c1[1] - bf16hi_f(ph[2]));
                pl[3] = pack_bf16(c1[2] - bf16lo_f(ph[3]), c1[3] - bf16hi_f(ph[3]));
#pragma unroll
                for (int dn = 0; dn < 8; dn++) {
                    mma16816(accO[ms][dn], ph, vh[dn][0], vh[dn][1]);
                    mma16816(accO[ms][dn], pl, vh[dn][0], vh[dn][1]);
                    mma16816(accO[ms][dn], ph, vl[dn][0], vl[dn][1]);
                }
            }
        }
        __syncthreads();
    }

    // ---- ctx epilogue: cross-wn reduce in smem, split store [B,S,D] ----
    float* st = (float*)dsm;                     // [128][65] fp32
    {
        const int lc2 = lc * 2;
        if (wn == 0) {
#pragma unroll
            for (int ms = 0; ms < 2; ms++)
#pragma unroll
                for (int dn = 0; dn < 8; dn++) {
                    int r = wm * 32 + ms * 16 + lr;
                    int c = dn * 8 + lc2;
                    st[r * 65 + c]           = accO[ms][dn][0];
                    st[r * 65 + c + 1]       = accO[ms][dn][1];
                    st[(r + 8) * 65 + c]     = accO[ms][dn][2];
                    st[(r + 8) * 65 + c + 1] = accO[ms][dn][3];
                }
        }
        __syncthreads();
        if (wn == 1) {
#pragma unroll
            for (int ms = 0; ms < 2; ms++)
#pragma unroll
                for (int dn = 0; dn < 8; dn++) {
                    int r = wm * 32 + ms * 16 + lr;
                    int c = dn * 8 + lc2;
                    st[r * 65 + c]           += accO[ms][dn][0];
                    st[r * 65 + c + 1]       += accO[ms][dn][1];
                    st[(r + 8) * 65 + c]     += accO[ms][dn][2];
                    st[(r + 8) * 65 + c + 1] += accO[ms][dn][3];
                }
        }
        __syncthreads();
    }
    {
        const int b = z >> 4, hh = z & 15;
        for (int i = tid; i < 128 * 64; i += 256) {
            int row = i >> 6, c = i & 63;
            float v = st[row * 65 + c];
            long o = (long)((b << 11) + m0 + row) * 1024 + hh * 64 + c;
            __nv_bfloat16 h = __float2bfloat16(v);
            ch[o] = h;
            cl[o] = __float2bfloat16(v - __bfloat162float(h));
        }
    }
}

// ---------------------------------------------------------------------------
extern "C" void kernel_launch(void* const* d_in, const int* in_sizes, int n_in,
                              void* d_out, int out_size)
{
    const float* Q  = (const float*)d_in[0];
    const float* K  = (const float*)d_in[1];
    const float* V  = (const float*)d_in[2];
    const float* Wq = (const float*)d_in[3];
    const float* bq = (const float*)d_in[4];
    const float* Wk = (const float*)d_in[5];
    const float* bk = (const float*)d_in[6];
    const float* Wv = (const float*)d_in[7];
    const float* bv = (const float*)d_in[8];
    const float* Wo = (const float*)d_in[9];
    const float* bo = (const float*)d_in[10];
    float* out = (float*)d_out;

    __nv_bfloat16 *Qh, *Ql, *Kh, *Kl, *Vh, *Vl;
    __nv_bfloat16 *Wqh, *Wql, *Wkh, *Wkl, *Wvh, *Wvl, *Woh, *Wol;
    __nv_bfloat16 *qh, *ql, *kh, *kl, *vth, *vtl, *ch, *cl;
    float* attn_scratch;
    cudaGetSymbolAddress((void**)&Qh, g_Qh);   cudaGetSymbolAddress((void**)&Ql, g_Ql);
    cudaGetSymbolAddress((void**)&Kh, g_Kh);   cudaGetSymbolAddress((void**)&Kl, g_Kl);
    cudaGetSymbolAddress((void**)&Vh, g_Vh);   cudaGetSymbolAddress((void**)&Vl, g_Vl);
    cudaGetSymbolAddress((void**)&Wqh, g_Wqh); cudaGetSymbolAddress((void**)&Wql, g_Wql);
    cudaGetSymbolAddress((void**)&Wkh, g_Wkh); cudaGetSymbolAddress((void**)&Wkl, g_Wkl);
    cudaGetSymbolAddress((void**)&Wvh, g_Wvh); cudaGetSymbolAddress((void**)&Wvl, g_Wvl);
    cudaGetSymbolAddress((void**)&Woh, g_Woh); cudaGetSymbolAddress((void**)&Wol, g_Wol);
    cudaGetSymbolAddress((void**)&qh, g_qh);   cudaGetSymbolAddress((void**)&ql, g_ql);
    cudaGetSymbolAddress((void**)&kh, g_kh);   cudaGetSymbolAddress((void**)&kl, g_kl);
    cudaGetSymbolAddress((void**)&vth, g_vth); cudaGetSymbolAddress((void**)&vtl, g_vtl);
    cudaGetSymbolAddress((void**)&ch, g_ch);   cudaGetSymbolAddress((void**)&cl, g_cl);
    cudaGetSymbolAddress((void**)&attn_scratch, g_attn);

    float* attn = ((long)out_size >= OUT_TOTAL) ? (out + OUT0) : attn_scratch;

    cudaFuncSetAttribute(mma_gemm<0>, cudaFuncAttributeMaxDynamicSharedMemorySize, SM_PIPE);
    cudaFuncSetAttribute(mma_gemm<1>, cudaFuncAttributeMaxDynamicSharedMemorySize, SM_PIPE);
    cudaFuncSetAttribute(mma_gemm<4>, cudaFuncAttributeMaxDynamicSharedMemorySize, SM_PIPE);
    cudaFuncSetAttribute(fused_attn_k, cudaFuncAttributeMaxDynamicSharedMemorySize, FB_SM);

    // 0) Split all GEMM inputs to bf16 hi/lo
    const int NI = TOKENS * DMODEL, NW = DMODEL * DMODEL;
    split_k<<<NI / 256, 256>>>(Q, Qh, Ql, NI);
    split_k<<<NI / 256, 256>>>(K, Kh, Kl, NI);
    split_k<<<NI / 256, 256>>>(V, Vh, Vl, NI);
    split_k<<<NW / 256, 256>>>(Wq, Wqh, Wql, NW);
    split_k<<<NW / 256, 256>>>(Wk, Wkh, Wkl, NW);
    split_k<<<NW / 256, 256>>>(Wv, Wvh, Wvl, NW);
    split_k<<<NW / 256, 256>>>(Wo, Woh, Wol, NW);

    // 1-3) Projections: [4096,1024] @ W^T + b (pipelined)
    dim3 gp(DMODEL / NT, TOKENS / MT, 1);                       // (16, 32)
    mma_gemm<0><<<gp, 256, SM_PIPE>>>(Qh, Ql, Wqh, Wql, bq, nullptr, qh, ql,
                                      DMODEL, DMODEL, DMODEL);
    mma_gemm<0><<<gp, 256, SM_PIPE>>>(Kh, Kl, Wkh, Wkl, bk, nullptr, kh, kl,
                                      DMODEL, DMODEL, DMODEL);
    mma_gemm<1><<<gp, 256, SM_PIPE>>>(Vh, Vl, Wvh, Wvl, bv, nullptr, vth, vtl,
                                      DMODEL, DMODEL, DMODEL);

    // 4) Fused scores + softmax + context
    dim3 gf(SEQ / 128, BH, 1);                                  // (16, 32)
    fused_attn_k<<<gf, 256, FB_SM>>>(qh, ql, kh, kl, vth, vtl, attn, ch, cl);

    // 5) Output projection: ctx @ Wo^T + bo -> out fp32 (pipelined)
    mma_gemm<4><<<gp, 256, SM_PIPE>>>(ch, cl, Woh, Wol, bo, out, nullptr, nullptr,
                                      DMODEL, DMODEL, DMODEL);

    (void)n_in; (void)in_sizes;
}